// round 3
// baseline (speedup 1.0000x reference)
#include <cuda_runtime.h>
#include <cstdint>

// Problem constants
#define BS    8
#define NN    2048
#define DIN   256
#define HH    128
#define ALPHA 0.2f

// Scratch (device globals: no allocation allowed)
__device__ float g_h[BS * NN * HH];    // 8 MB: h = x @ W^T
__device__ float g_ss[BS * NN];        // s_self
__device__ float g_sn[BS * NN];        // s_nb

// ============================================================================
// Kernel 1: h[b,n,c] = sum_d x[b,n,d] * W[c,d]
// Block: 256 threads, tile = 32 rows x 128 cols, d-chunked (64) through smem.
// Micro-tile 4x4 per thread.
// ============================================================================
#define K1_TI 32
#define K1_DC 64
__global__ __launch_bounds__(256) void k1_hgemm(const float* __restrict__ x,
                                                const float* __restrict__ W) {
    __shared__ float sWt[K1_DC][132];  // Wt[d][c], pad 132 (528B rows: 16B-aligned, bank-skewed)
    __shared__ float sxt[K1_DC][36];   // xt[d][i], pad 36 (144B rows)

    const int b    = blockIdx.y;
    const int row0 = blockIdx.x * K1_TI;
    const int tid  = threadIdx.x;
    const int cg   = tid & 31;   // c0 = cg*4  (32 groups x 4 = 128 cols)
    const int ig   = tid >> 5;   // i0 = ig*4  (8 groups x 4 = 32 rows)

    float acc[4][4];
#pragma unroll
    for (int r = 0; r < 4; r++)
#pragma unroll
        for (int c = 0; c < 4; c++) acc[r][c] = 0.f;

    const float* xb = x + ((size_t)b * NN + row0) * DIN;

    const int d_l = tid & 63;   // 0..63
    const int cc  = tid >> 6;   // 0..3

    for (int d0 = 0; d0 < DIN; d0 += K1_DC) {
        __syncthreads();
        // Load W chunk (transposed): coalesced global reads, skewed smem stores
#pragma unroll
        for (int p = 0; p < 32; p++) {
            int c = cc + p * 4;
            sWt[d_l][c] = W[c * DIN + d0 + d_l];
        }
        // Load x chunk (transposed)
#pragma unroll
        for (int p = 0; p < 8; p++) {
            int i = cc + p * 4;
            sxt[d_l][i] = xb[(size_t)i * DIN + d0 + d_l];
        }
        __syncthreads();

#pragma unroll 8
        for (int d = 0; d < K1_DC; d++) {
            float4 xv = *(const float4*)&sxt[d][ig * 4];
            float4 wv = *(const float4*)&sWt[d][cg * 4];
            float xr[4] = {xv.x, xv.y, xv.z, xv.w};
            float wc[4] = {wv.x, wv.y, wv.z, wv.w};
#pragma unroll
            for (int r = 0; r < 4; r++)
#pragma unroll
                for (int c = 0; c < 4; c++) acc[r][c] += xr[r] * wc[c];
        }
    }

    float* hb = g_h + ((size_t)b * NN + row0) * HH;
#pragma unroll
    for (int r = 0; r < 4; r++) {
        float4 v = make_float4(acc[r][0], acc[r][1], acc[r][2], acc[r][3]);
        *(float4*)&hb[(size_t)(ig * 4 + r) * HH + cg * 4] = v;
    }
}

// ============================================================================
// Kernel 2: s_self[row] = h[row,:] . a[0:128],  s_nb[row] = h[row,:] . a[128:256]
// 1 warp per row, 8 rows per 256-thread block.
// ============================================================================
__global__ __launch_bounds__(256) void k2_scores(const float* __restrict__ a) {
    const int warp = threadIdx.x >> 5;
    const int lane = threadIdx.x & 31;
    const int row  = blockIdx.x * 8 + warp;   // 0 .. BS*NN-1

    float4 h  = ((const float4*)(g_h + (size_t)row * HH))[lane];
    float4 as = ((const float4*)a)[lane];
    float4 an = ((const float4*)(a + HH))[lane];

    float ss = h.x * as.x + h.y * as.y + h.z * as.z + h.w * as.w;
    float sn = h.x * an.x + h.y * an.y + h.z * an.z + h.w * an.w;
#pragma unroll
    for (int o = 16; o; o >>= 1) {
        ss += __shfl_xor_sync(0xffffffffu, ss, o);
        sn += __shfl_xor_sync(0xffffffffu, sn, o);
    }
    if (lane == 0) {
        g_ss[row] = ss;
        g_sn[row] = sn;
    }
}

// ============================================================================
// Kernel 3: fused masked-softmax aggregation.
//   w[i,j] = adj[b,i,j] ? exp(lrelu(ss[i] + sn[j])) : 0
//   out[b,i,:] = elu( (sum_j w[i,j] * h[b,j,:]) / (sum_j w[i,j]) )
// Block: 128 threads, output tile 64 rows x 128 cols, TJ=32 j-steps.
// Thread micro-tile: 8x8 via split mapping rows {ig*4, 32+ig*4}, cols
// {cg*4, 64+cg*4} so every LDS.128 phase-octet covers 128 contiguous bytes.
// ============================================================================
#define TI 64
#define TJ 32
__global__ __launch_bounds__(128, 3) void k3_attn(const float* __restrict__ adj,
                                                  float* __restrict__ out) {
    __shared__ float sh_h[TJ][HH];       // 16 KB, rows 512B (16B aligned)
    __shared__ float sh_w[TJ][68];       // 8.5 KB, rows 272B (16B aligned, skewed)
    __shared__ float sh_den[TI];
    __shared__ float sh_ss[TI];

    const int b    = blockIdx.y;
    const int i0g  = blockIdx.x * TI;
    const int tid  = threadIdx.x;
    const int lane = tid & 31;
    const int wid  = tid >> 5;   // 0..3
    const int cg   = tid & 15;   // col groups: cols cg*4 and 64+cg*4
    const int ig   = tid >> 4;   // row groups 0..7: rows ig*4 and 32+ig*4

    if (tid < TI) sh_ss[tid] = g_ss[b * NN + i0g + tid];

    float acc[8][8];
#pragma unroll
    for (int r = 0; r < 8; r++)
#pragma unroll
        for (int c = 0; c < 8; c++) acc[r][c] = 0.f;

    float den[16];
#pragma unroll
    for (int k = 0; k < 16; k++) den[k] = 0.f;

    const float* adjb = adj + ((size_t)b * NN + i0g) * NN;
    const float* hb   = g_h + (size_t)b * NN * HH;
    const float* snb  = g_sn + b * NN;

    __syncthreads();  // sh_ss visible

    for (int j0 = 0; j0 < NN; j0 += TJ) {
        __syncthreads();  // previous compute done before overwrite

        // --- load h tile (32x128 floats, contiguous) ---
        const float4* hsrc = (const float4*)(hb + (size_t)j0 * HH);
#pragma unroll
        for (int p = 0; p < 8; p++) {
            int idx = tid + p * 128;              // 1024 float4s total
            ((float4*)sh_h)[idx] = hsrc[idx];
        }

        // --- generate w tile: warp wid handles rows wid*16..+15, lane = j ---
        {
            float sn = snb[j0 + lane];
#pragma unroll
            for (int ii = 0; ii < 16; ii++) {
                int   i_loc = wid * 16 + ii;
                float av    = adjb[(size_t)i_loc * NN + j0 + lane];
                float e     = sh_ss[i_loc] + sn;
                e           = (e >= 0.f) ? e : (ALPHA * e);
                float wv    = (av != 0.f) ? __expf(e) : 0.f;
                den[ii] += wv;
                sh_w[lane][i_loc] = wv;
            }
        }
        __syncthreads();

        // --- rank-TJ accumulation: 64 FMA per 64B of LDS per thread per j ---
#pragma unroll 4
        for (int j = 0; j < TJ; j++) {
            float4 w0 = *(const float4*)&sh_w[j][ig * 4];
            float4 w1 = *(const float4*)&sh_w[j][32 + ig * 4];
            float4 h0 = *(const float4*)&sh_h[j][cg * 4];
            float4 h1 = *(const float4*)&sh_h[j][64 + cg * 4];
            float wr[8] = {w0.x, w0.y, w0.z, w0.w, w1.x, w1.y, w1.z, w1.w};
            float hc[8] = {h0.x, h0.y, h0.z, h0.w, h1.x, h1.y, h1.z, h1.w};
#pragma unroll
            for (int r = 0; r < 8; r++)
#pragma unroll
                for (int c = 0; c < 8; c++) acc[r][c] += wr[r] * hc[c];
        }
    }

    // --- reduce row denominators (lane-private partials over all j) ---
#pragma unroll
    for (int ii = 0; ii < 16; ii++) {
        float v = den[ii];
#pragma unroll
        for (int o = 16; o; o >>= 1) v += __shfl_xor_sync(0xffffffffu, v, o);
        if (lane == 0) sh_den[wid * 16 + ii] = v;
    }
    __syncthreads();

    // --- epilogue: normalize, ELU, store ---
    float* ob = out + ((size_t)b * NN + i0g) * HH;
#pragma unroll
    for (int rr = 0; rr < 8; rr++) {
        int   rloc = (rr < 4) ? (ig * 4 + rr) : (32 + ig * 4 + (rr - 4));
        float inv  = 1.f / sh_den[rloc];
        float o0[4], o1[4];
#pragma unroll
        for (int c = 0; c < 4; c++) {
            float v0 = acc[rr][c] * inv;
            float v1 = acc[rr][c + 4] * inv;
            o0[c] = (v0 > 0.f) ? v0 : expm1f(v0);
            o1[c] = (v1 > 0.f) ? v1 : expm1f(v1);
        }
        float* orow = ob + (size_t)rloc * HH;
        *(float4*)&orow[cg * 4]      = make_float4(o0[0], o0[1], o0[2], o0[3]);
        *(float4*)&orow[64 + cg * 4] = make_float4(o1[0], o1[1], o1[2], o1[3]);
    }
}

// ============================================================================
// Launch
// ============================================================================
extern "C" void kernel_launch(void* const* d_in, const int* in_sizes, int n_in,
                              void* d_out, int out_size) {
    const float* x   = (const float*)d_in[0];  // [8, 2048, 256]
    const float* adj = (const float*)d_in[1];  // [8, 2048, 2048]
    const float* W   = (const float*)d_in[2];  // [128, 256]
    const float* a   = (const float*)d_in[3];  // [256]
    float*       out = (float*)d_out;          // [8, 2048, 128]

    k1_hgemm<<<dim3(NN / K1_TI, BS), 256>>>(x, W);
    k2_scores<<<(BS * NN) / 8, 256>>>(a);
    k3_attn<<<dim3(NN / TI, BS), 128>>>(adj, out);
}

// round 5
// speedup vs baseline: 1.2130x; 1.2130x over previous
#include <cuda_runtime.h>
#include <cstdint>

// Problem constants
#define BS    8
#define NN    2048
#define DIN   256
#define HH    128
#define ALPHA 0.2f

// Scratch (device globals: no allocation allowed)
__device__ float g_ht[BS * HH * NN];   // 8 MB: h^T  [b][c][n]
__device__ float g_ss[BS * NN];        // s_self
__device__ float g_sn[BS * NN];        // s_nb

// round-to-nearest fp32 -> tf32 bit pattern (low mantissa zeroed)
static __device__ __forceinline__ uint32_t tf32rn(float x) {
    uint32_t r;
    asm("cvt.rna.tf32.f32 %0, %1;" : "=r"(r) : "f"(x));
    return r;
}

// D += A(16x8, row-major) * B(8x8, col-major), tf32 inputs, fp32 accum
static __device__ __forceinline__ void mma_tf32(float* c, const uint32_t* a,
                                                const uint32_t* b) {
    asm volatile(
        "mma.sync.aligned.m16n8k8.row.col.f32.tf32.tf32.f32 "
        "{%0,%1,%2,%3}, {%4,%5,%6,%7}, {%8,%9}, {%0,%1,%2,%3};"
        : "+f"(c[0]), "+f"(c[1]), "+f"(c[2]), "+f"(c[3])
        : "r"(a[0]), "r"(a[1]), "r"(a[2]), "r"(a[3]), "r"(b[0]), "r"(b[1]));
}

// ============================================================================
// Kernel 1: h = x @ W^T, fused score dots, transposed store to g_ht.
// Block: 256 threads, tile = 32 rows x 128 cols, d-chunked (64) through smem.
// ============================================================================
#define K1_TI 32
#define K1_DC 64
__global__ __launch_bounds__(256) void k1_hgemm(const float* __restrict__ x,
                                                const float* __restrict__ W,
                                                const float* __restrict__ a) {
    __shared__ float sWt[K1_DC][132];
    __shared__ float sxt[K1_DC][36];

    const int b    = blockIdx.y;
    const int row0 = blockIdx.x * K1_TI;
    const int tid  = threadIdx.x;
    const int cg   = tid & 31;
    const int ig   = tid >> 5;

    float acc[4][4];
#pragma unroll
    for (int r = 0; r < 4; r++)
#pragma unroll
        for (int c = 0; c < 4; c++) acc[r][c] = 0.f;

    const float* xb = x + ((size_t)b * NN + row0) * DIN;
    const int d_l = tid & 63;
    const int cc  = tid >> 6;

    for (int d0 = 0; d0 < DIN; d0 += K1_DC) {
        __syncthreads();
#pragma unroll
        for (int p = 0; p < 32; p++) {
            int c = cc + p * 4;
            sWt[d_l][c] = W[c * DIN + d0 + d_l];
        }
#pragma unroll
        for (int p = 0; p < 8; p++) {
            int i = cc + p * 4;
            sxt[d_l][i] = xb[(size_t)i * DIN + d0 + d_l];
        }
        __syncthreads();

#pragma unroll 8
        for (int d = 0; d < K1_DC; d++) {
            float4 xv = *(const float4*)&sxt[d][ig * 4];
            float4 wv = *(const float4*)&sWt[d][cg * 4];
            float xr[4] = {xv.x, xv.y, xv.z, xv.w};
            float wc[4] = {wv.x, wv.y, wv.z, wv.w};
#pragma unroll
            for (int r = 0; r < 4; r++)
#pragma unroll
                for (int c = 0; c < 4; c++) acc[r][c] += xr[r] * wc[c];
        }
    }

    // --- transposed store: g_ht[b][c][n] ---
    float* htb = g_ht + (size_t)b * HH * NN;
#pragma unroll
    for (int c = 0; c < 4; c++) {
        float4 v = make_float4(acc[0][c], acc[1][c], acc[2][c], acc[3][c]);
        *(float4*)&htb[(size_t)(cg * 4 + c) * NN + row0 + ig * 4] = v;
    }

    // --- fused score dots: ss = h . a[0:128], sn = h . a[128:256] ---
    float4 av_s = ((const float4*)a)[cg];
    float4 av_n = ((const float4*)(a + HH))[cg];
    float as[4] = {av_s.x, av_s.y, av_s.z, av_s.w};
    float an[4] = {av_n.x, av_n.y, av_n.z, av_n.w};
#pragma unroll
    for (int r = 0; r < 4; r++) {
        float ss = 0.f, sn = 0.f;
#pragma unroll
        for (int c = 0; c < 4; c++) {
            ss += acc[r][c] * as[c];
            sn += acc[r][c] * an[c];
        }
#pragma unroll
        for (int o = 16; o; o >>= 1) {
            ss += __shfl_xor_sync(0xffffffffu, ss, o);
            sn += __shfl_xor_sync(0xffffffffu, sn, o);
        }
        if (cg == 0) {
            int row = row0 + ig * 4 + r;
            g_ss[b * NN + row] = ss;
            g_sn[b * NN + row] = sn;
        }
    }
}

// ============================================================================
// Kernel 3: fused masked-softmax aggregation on mma.sync tf32.
//   w[i,j] = adj ? exp(lrelu(ss[i]+sn[j])) : 0   (tf32-rounded; den sums the
//   SAME rounded values so the softmax ratio is consistent)
//   out[b,i,:] = elu( (W_attn @ h) / den )
// CTA: 128 i-rows x 128 features, K=2048 in chunks of 32. 256 threads.
// Warp grid 4x2: each warp owns M32 x N64 = 2x8 m16n8k8 tiles.
// Pad-36 smem rows -> conflict-free fragment LDS (banks 4*(lane>>2)+(lane&3)).
// ============================================================================
#define K3_TJ 32
#define K3_LD 36
__global__ __launch_bounds__(256) void k3_attn(const float* __restrict__ adj,
                                               float* __restrict__ out) {
    __shared__ uint32_t smA[128][K3_LD];  // w tile:  [i][k]   (A, row-major)
    __shared__ uint32_t smB[128][K3_LD];  // h tile:  [n][k]   (B, col-major)
    __shared__ float sh_ss[128];
    __shared__ float sh_den[128];

    const int b    = blockIdx.y;
    const int i0   = blockIdx.x * 128;
    const int tid  = threadIdx.x;
    const int wid  = tid >> 5;       // 0..7
    const int lane = tid & 31;
    const int gr   = lane >> 2;      // 0..7
    const int kq   = lane & 3;       // 0..3

    const int warp_m = wid & 3;      // M block: rows warp_m*32..+31
    const int warp_n = wid >> 2;     // N block: cols warp_n*64..+63

    if (tid < 128) sh_ss[tid] = g_ss[b * NN + i0 + tid];

    float acc[2][8][4];
#pragma unroll
    for (int mt = 0; mt < 2; mt++)
#pragma unroll
        for (int nt = 0; nt < 8; nt++)
#pragma unroll
            for (int q = 0; q < 4; q++) acc[mt][nt][q] = 0.f;

    float den[16];
#pragma unroll
    for (int q = 0; q < 16; q++) den[q] = 0.f;

    // gen mapping: warp wid owns rows wid*16..wid*16+15, lane = k-column
    const float* adjw = adj + ((size_t)(b * NN + i0 + wid * 16)) * NN;
    const float* snb  = g_sn + b * NN;
    const float* htb  = g_ht + (size_t)b * HH * NN;

    __syncthreads();  // sh_ss visible

    for (int j0 = 0; j0 < NN; j0 += K3_TJ) {
        __syncthreads();  // previous chunk's MMA reads complete

        // ---- B tile: smB[c][k] = tf32(h^T[c][j0+k]); 1024 float4 loads ----
#pragma unroll
        for (int p = 0; p < 4; p++) {
            int flat = p * 256 + tid;     // 0..1023
            int row  = flat >> 3;         // feature c
            int f4   = flat & 7;          // k-quad
            float4 v = ((const float4*)(htb + (size_t)row * NN + j0))[f4];
            uint4 u;
            u.x = tf32rn(v.x); u.y = tf32rn(v.y);
            u.z = tf32rn(v.z); u.w = tf32rn(v.w);
            *(uint4*)&smB[row][f4 * 4] = u;
        }

        // ---- A tile: w gen, 16 rows per warp, lane = k ----
        {
            float sn = snb[j0 + lane];
#pragma unroll
            for (int ii = 0; ii < 16; ii++) {
                float av = adjw[(size_t)ii * NN + j0 + lane];
                float e  = sh_ss[wid * 16 + ii] + sn;
                e = (e >= 0.f) ? e : (ALPHA * e);
                float wv = (av != 0.f) ? __expf(e) : 0.f;
                uint32_t wr = tf32rn(wv);
                den[ii] += __uint_as_float(wr);
                smA[wid * 16 + ii][lane] = wr;
            }
        }
        __syncthreads();

        // ---- MMA: 4 k-steps x (2 M-tiles x 8 N-tiles) ----
#pragma unroll
        for (int k0 = 0; k0 < K3_TJ; k0 += 8) {
            uint32_t afrag[2][4];
#pragma unroll
            for (int mt = 0; mt < 2; mt++) {
                int i = warp_m * 32 + mt * 16 + gr;
                afrag[mt][0] = smA[i][k0 + kq];
                afrag[mt][1] = smA[i + 8][k0 + kq];
                afrag[mt][2] = smA[i][k0 + kq + 4];
                afrag[mt][3] = smA[i + 8][k0 + kq + 4];
            }
            uint32_t bfrag[8][2];
#pragma unroll
            for (int nt = 0; nt < 8; nt++) {
                int n = warp_n * 64 + nt * 8 + gr;
                bfrag[nt][0] = smB[n][k0 + kq];
                bfrag[nt][1] = smB[n][k0 + kq + 4];
            }
#pragma unroll
            for (int mt = 0; mt < 2; mt++)
#pragma unroll
                for (int nt = 0; nt < 8; nt++)
                    mma_tf32(acc[mt][nt], afrag[mt], bfrag[nt]);
        }
    }

    // ---- denominators (exact fp32 over rounded w) ----
#pragma unroll
    for (int ii = 0; ii < 16; ii++) {
        float v = den[ii];
#pragma unroll
        for (int o = 16; o; o >>= 1) v += __shfl_xor_sync(0xffffffffu, v, o);
        if (lane == 0) sh_den[wid * 16 + ii] = v;
    }
    __syncthreads();

    // ---- epilogue: normalize, ELU, store ----
    // acc[mt][nt]: c0=(r,2c) c1=(r,2c+1) c2=(r+8,2c) c3=(r+8,2c+1),
    // r = gr, c = kq, within tile (warp_m*32+mt*16, warp_n*64+nt*8)
#pragma unroll
    for (int mt = 0; mt < 2; mt++) {
        int   rA   = warp_m * 32 + mt * 16 + gr;
        int   rB   = rA + 8;
        float invA = 1.f / sh_den[rA];
        float invB = 1.f / sh_den[rB];
        float* oA  = out + ((size_t)(b * NN + i0 + rA)) * HH + warp_n * 64;
        float* oB  = out + ((size_t)(b * NN + i0 + rB)) * HH + warp_n * 64;
#pragma unroll
        for (int nt = 0; nt < 8; nt++) {
            float v0 = acc[mt][nt][0] * invA;
            float v1 = acc[mt][nt][1] * invA;
            float v2 = acc[mt][nt][2] * invB;
            float v3 = acc[mt][nt][3] * invB;
            float2 pA, pB;
            pA.x = (v0 > 0.f) ? v0 : expm1f(v0);
            pA.y = (v1 > 0.f) ? v1 : expm1f(v1);
            pB.x = (v2 > 0.f) ? v2 : expm1f(v2);
            pB.y = (v3 > 0.f) ? v3 : expm1f(v3);
            *(float2*)&oA[nt * 8 + kq * 2] = pA;
            *(float2*)&oB[nt * 8 + kq * 2] = pB;
        }
    }
}

// ============================================================================
// Launch
// ============================================================================
extern "C" void kernel_launch(void* const* d_in, const int* in_sizes, int n_in,
                              void* d_out, int out_size) {
    const float* x   = (const float*)d_in[0];  // [8, 2048, 256]
    const float* adj = (const float*)d_in[1];  // [8, 2048, 2048]
    const float* W   = (const float*)d_in[2];  // [128, 256]
    const float* a   = (const float*)d_in[3];  // [256]
    float*       out = (float*)d_out;          // [8, 2048, 128]

    k1_hgemm<<<dim3(NN / K1_TI, BS), 256>>>(x, W, a);
    k3_attn<<<dim3(NN / 128, BS), 256>>>(adj, out);
}

// round 7
// speedup vs baseline: 2.9893x; 2.4643x over previous
#include <cuda_runtime.h>
#include <cstdint>

// Problem constants
#define BS    8
#define NN    2048
#define DIN   256
#define HH    128
#define ALPHA 0.2f

// Scratch (device globals: no allocation allowed)
__device__ float g_ht[BS * HH * NN];   // 8 MB: h^T [b][c][n], tf32-rounded
__device__ float g_ss[BS * NN];        // s_self
__device__ float g_sn[BS * NN];        // s_nb

static __device__ __forceinline__ uint32_t smem_u32(const void* p) {
    uint32_t r;
    asm("{ .reg .u64 t; cvta.to.shared.u64 t, %1; cvt.u32.u64 %0, t; }"
        : "=r"(r) : "l"(p));
    return r;
}

static __device__ __forceinline__ uint32_t tf32rn(float x) {
    uint32_t r;
    asm("cvt.rna.tf32.f32 %0, %1;" : "=r"(r) : "f"(x));
    return r;
}

#define CP_ASYNC16(dst_u32, src_ptr) \
    asm volatile("cp.async.cg.shared.global [%0], [%1], 16;" \
                 :: "r"(dst_u32), "l"(src_ptr) : "memory")
#define CP_COMMIT()  asm volatile("cp.async.commit_group;" ::: "memory")
#define CP_WAIT0()   asm volatile("cp.async.wait_group 0;" ::: "memory")

// D += A(16x8 row-major) * B(8x8 col-major), tf32 in, fp32 accum
static __device__ __forceinline__ void mma_tf32(float* c, const uint32_t* a,
                                                const uint32_t* b) {
    asm volatile(
        "mma.sync.aligned.m16n8k8.row.col.f32.tf32.tf32.f32 "
        "{%0,%1,%2,%3}, {%4,%5,%6,%7}, {%8,%9}, {%0,%1,%2,%3};"
        : "+f"(c[0]), "+f"(c[1]), "+f"(c[2]), "+f"(c[3])
        : "r"(a[0]), "r"(a[1]), "r"(a[2]), "r"(a[3]), "r"(b[0]), "r"(b[1]));
}

#define PAD 36  // row stride (floats): conflict-free frag LDS + 16B-aligned rows

// ============================================================================
// Kernel 1: h = x @ W^T on tf32 mma. CTA: 128 n-rows x 128 c-cols, K=256.
// Epilogue: scatter tf32(h) to g_ht (transposed) + fused ss/sn dots.
// Warp grid 4x2 (warp_m 0..3, warp_n 0..1), per-warp M32xN64, acc[2][8][4].
// ============================================================================
__global__ __launch_bounds__(256) void k1_hgemm(const float* __restrict__ x,
                                                const float* __restrict__ W,
                                                const float* __restrict__ a) {
    __shared__ uint32_t sA[128][PAD];   // x tile  [n][d]
    __shared__ uint32_t sB[128][PAD];   // W tile  [c][d]
    __shared__ float sh_ps[2][128];
    __shared__ float sh_pn[2][128];

    const int b    = blockIdx.y;
    const int row0 = blockIdx.x * 128;
    const int tid  = threadIdx.x;
    const int wid  = tid >> 5;
    const int lane = tid & 31;
    const int gr   = lane >> 2;
    const int kq   = lane & 3;
    const int warp_m = wid & 3;
    const int warp_n = wid >> 2;

    float acc[2][8][4];
#pragma unroll
    for (int mt = 0; mt < 2; mt++)
#pragma unroll
        for (int nt = 0; nt < 8; nt++)
#pragma unroll
            for (int q = 0; q < 4; q++) acc[mt][nt][q] = 0.f;

    const float* xb = x + ((size_t)b * NN + row0) * DIN;

    for (int d0 = 0; d0 < DIN; d0 += 32) {
        __syncthreads();
#pragma unroll
        for (int p = 0; p < 4; p++) {
            int flat = p * 256 + tid;   // 0..1023
            int row  = flat >> 3;
            int q8   = flat & 7;
            float4 xv = *(const float4*)(xb + (size_t)row * DIN + d0 + q8 * 4);
            uint4 u;
            u.x = tf32rn(xv.x); u.y = tf32rn(xv.y);
            u.z = tf32rn(xv.z); u.w = tf32rn(xv.w);
            *(uint4*)&sA[row][q8 * 4] = u;
            float4 wv = *(const float4*)(W + (size_t)row * DIN + d0 + q8 * 4);
            u.x = tf32rn(wv.x); u.y = tf32rn(wv.y);
            u.z = tf32rn(wv.z); u.w = tf32rn(wv.w);
            *(uint4*)&sB[row][q8 * 4] = u;
        }
        __syncthreads();

#pragma unroll
        for (int k0 = 0; k0 < 32; k0 += 8) {
            uint32_t afrag[2][4];
#pragma unroll
            for (int mt = 0; mt < 2; mt++) {
                int i = warp_m * 32 + mt * 16 + gr;
                afrag[mt][0] = sA[i][k0 + kq];
                afrag[mt][1] = sA[i + 8][k0 + kq];
                afrag[mt][2] = sA[i][k0 + kq + 4];
                afrag[mt][3] = sA[i + 8][k0 + kq + 4];
            }
            uint32_t bfrag[8][2];
#pragma unroll
            for (int nt = 0; nt < 8; nt++) {
                int n = warp_n * 64 + nt * 8 + gr;
                bfrag[nt][0] = sB[n][k0 + kq];
                bfrag[nt][1] = sB[n][k0 + kq + 4];
            }
#pragma unroll
            for (int mt = 0; mt < 2; mt++)
#pragma unroll
                for (int nt = 0; nt < 8; nt++)
                    mma_tf32(acc[mt][nt], afrag[mt], bfrag[nt]);
        }
    }

    // ---- epilogue: scatter h^T (tf32-rounded) + ss/sn partial dots ----
    float* htb = g_ht + (size_t)b * HH * NN;
    float psA[2] = {0.f, 0.f}, pnA[2] = {0.f, 0.f};  // [mt] for row rA
    float psB[2] = {0.f, 0.f}, pnB[2] = {0.f, 0.f};  // [mt] for row rB
#pragma unroll
    for (int mt = 0; mt < 2; mt++) {
        int nA = row0 + warp_m * 32 + mt * 16 + gr;
        int nB = nA + 8;
#pragma unroll
        for (int nt = 0; nt < 8; nt++) {
            int c0 = warp_n * 64 + nt * 8 + kq * 2;
            float as0 = a[c0], as1 = a[c0 + 1];
            float an0 = a[HH + c0], an1 = a[HH + c0 + 1];
            float v0 = acc[mt][nt][0], v1 = acc[mt][nt][1];
            float v2 = acc[mt][nt][2], v3 = acc[mt][nt][3];
            psA[mt] += v0 * as0 + v1 * as1;
            pnA[mt] += v0 * an0 + v1 * an1;
            psB[mt] += v2 * as0 + v3 * as1;
            pnB[mt] += v2 * an0 + v3 * an1;
            htb[(size_t)c0 * NN + nA]       = __uint_as_float(tf32rn(v0));
            htb[(size_t)(c0 + 1) * NN + nA] = __uint_as_float(tf32rn(v1));
            htb[(size_t)c0 * NN + nB]       = __uint_as_float(tf32rn(v2));
            htb[(size_t)(c0 + 1) * NN + nB] = __uint_as_float(tf32rn(v3));
        }
    }
    // reduce over kq (lanes gr*4 + kq, kq in 0..3)
#pragma unroll
    for (int o = 1; o <= 2; o <<= 1) {
#pragma unroll
        for (int mt = 0; mt < 2; mt++) {
            psA[mt] += __shfl_xor_sync(0xffffffffu, psA[mt], o);
            pnA[mt] += __shfl_xor_sync(0xffffffffu, pnA[mt], o);
            psB[mt] += __shfl_xor_sync(0xffffffffu, psB[mt], o);
            pnB[mt] += __shfl_xor_sync(0xffffffffu, pnB[mt], o);
        }
    }
    if (kq == 0) {
#pragma unroll
        for (int mt = 0; mt < 2; mt++) {
            int rA = warp_m * 32 + mt * 16 + gr;
            sh_ps[warp_n][rA]     = psA[mt];
            sh_pn[warp_n][rA]     = pnA[mt];
            sh_ps[warp_n][rA + 8] = psB[mt];
            sh_pn[warp_n][rA + 8] = pnB[mt];
        }
    }
    __syncthreads();
    if (tid < 128) {
        g_ss[b * NN + row0 + tid] = sh_ps[0][tid] + sh_ps[1][tid];
        g_sn[b * NN + row0 + tid] = sh_pn[0][tid] + sh_pn[1][tid];
    }
}

// ============================================================================
// Kernel 3: masked-softmax aggregation, NO per-entry exp.
//   w[i,j] = adj * (E_i*F_j >= 1 ? E_i*F_j : G_i*H_j)    [tf32-rounded]
//   E=exp(ss), G=exp(.2ss) per row; F=exp(sn), H=exp(.2sn) tables per batch.
//   out = elu( (W @ h) / rowsum(w) )  via m16n8k8 tf32 mma.
// cp.async double-buffered adj + h tiles, prefetched one chunk ahead.
// ============================================================================
#define K3_CH 64   // chunks of 32 over K=2048
// dynamic smem layout (bytes)
#define OFF_SA   0                         // u32[2][128*PAD]
#define OFF_SB   (OFF_SA + 2*128*PAD*4)    // u32[2][128*PAD]
#define OFF_ADJ  (OFF_SB + 2*128*PAD*4)    // f32[2][128*32]
#define OFF_F    (OFF_ADJ + 2*128*32*4)    // f32[2048]
#define OFF_H    (OFF_F + 2048*4)          // f32[2048]
#define OFF_EG   (OFF_H + 2048*4)          // float2[128]
#define OFF_DEN  (OFF_EG + 128*8)          // f32[128]
#define K3_SMEM  (OFF_DEN + 128*4)

__global__ __launch_bounds__(256) void k3_attn(const float* __restrict__ adj,
                                               float* __restrict__ out) {
    extern __shared__ char dsm[];
    const uint32_t smb = smem_u32(dsm);

    uint32_t* smA   = (uint32_t*)(dsm + OFF_SA);
    uint32_t* smB   = (uint32_t*)(dsm + OFF_SB);
    float*    smAdj = (float*)(dsm + OFF_ADJ);
    float*    shF   = (float*)(dsm + OFF_F);
    float*    shH   = (float*)(dsm + OFF_H);
    float2*   shEG  = (float2*)(dsm + OFF_EG);
    float*    shDen = (float*)(dsm + OFF_DEN);

    const int b    = blockIdx.y;
    const int i0   = blockIdx.x * 128;
    const int tid  = threadIdx.x;
    const int wid  = tid >> 5;
    const int lane = tid & 31;
    const int gr   = lane >> 2;
    const int kq   = lane & 3;
    const int warp_m = wid & 3;
    const int warp_n = wid >> 2;

    const float* adjb = adj + ((size_t)b * NN + i0) * NN;
    const float* htb  = g_ht + (size_t)b * HH * NN;

    // per-thread cp.async src/dst mapping (4 x 16B for adj, 4 for B)
    const int crow[4] = {(0*256+tid) >> 3, (1*256+tid) >> 3,
                         (2*256+tid) >> 3, (3*256+tid) >> 3};
    const int cq     = tid & 7;   // 16B chunk within row (same for all p)

    // ---- prologue: issue chunk 0 into buf 0 ----
    {
#pragma unroll
        for (int p = 0; p < 4; p++) {
            int r = crow[p];
            CP_ASYNC16(smb + OFF_ADJ + (r * 32 + cq * 4) * 4,
                       adjb + (size_t)r * NN + cq * 4);
            CP_ASYNC16(smb + OFF_SB + (r * PAD + cq * 4) * 4,
                       htb + (size_t)r * NN + cq * 4);
        }
        CP_COMMIT();
    }

    // ---- tables (overlapped with cp.async flight) ----
#pragma unroll
    for (int p = 0; p < 8; p++) {
        int j = p * 256 + tid;
        float sn = g_sn[b * NN + j];
        shF[j] = expf(sn);
        shH[j] = expf(0.2f * sn);
    }
    if (tid < 128) {
        float ss = g_ss[b * NN + i0 + tid];
        shEG[tid] = make_float2(expf(ss), expf(0.2f * ss));
    }

    float acc[2][8][4];
#pragma unroll
    for (int mt = 0; mt < 2; mt++)
#pragma unroll
        for (int nt = 0; nt < 8; nt++)
#pragma unroll
            for (int q = 0; q < 4; q++) acc[mt][nt][q] = 0.f;

    float den[16];
#pragma unroll
    for (int q = 0; q < 16; q++) den[q] = 0.f;

    for (int t = 0; t < K3_CH; t++) {
        const int buf = t & 1;
        uint32_t* sAb   = smA + buf * (128 * PAD);
        uint32_t* sBb   = smB + buf * (128 * PAD);
        float*    sAdjb = smAdj + buf * (128 * 32);

        CP_WAIT0();
        __syncthreads();   // chunk-t data visible; also gates first-iter tables

        // ---- gen: w tile from adj + factored exp tables ----
        {
            float F = shF[t * 32 + lane];
            float H = shH[t * 32 + lane];
#pragma unroll
            for (int ii = 0; ii < 16; ii++) {
                int    r  = wid * 16 + ii;
                float  av = sAdjb[r * 32 + lane];
                float2 eg = shEG[r];
                float  p  = eg.x * F;
                float  w  = av * ((p >= 1.f) ? p : eg.y * H);
                uint32_t wr = tf32rn(w);
                den[ii] += __uint_as_float(wr);
                sAb[r * PAD + lane] = wr;
            }
        }
        __syncthreads();   // smA complete for all warps

        // ---- prefetch chunk t+1 (safe: globally past all MMA t-1 reads) ----
        if (t + 1 < K3_CH) {
            const int nb = (t + 1) & 1;
            const int j1 = (t + 1) * 32;
#pragma unroll
            for (int p = 0; p < 4; p++) {
                int r = crow[p];
                CP_ASYNC16(smb + OFF_ADJ + (nb * 128 * 32 + r * 32 + cq * 4) * 4,
                           adjb + (size_t)r * NN + j1 + cq * 4);
                CP_ASYNC16(smb + OFF_SB + (nb * 128 * PAD + r * PAD + cq * 4) * 4,
                           htb + (size_t)r * NN + j1 + cq * 4);
            }
        }
        CP_COMMIT();

        // ---- MMA: 4 k-steps x (2 M x 8 N) ----
#pragma unroll
        for (int k0 = 0; k0 < 32; k0 += 8) {
            uint32_t afrag[2][4];
#pragma unroll
            for (int mt = 0; mt < 2; mt++) {
                int i = warp_m * 32 + mt * 16 + gr;
                afrag[mt][0] = sAb[i * PAD + k0 + kq];
                afrag[mt][1] = sAb[(i + 8) * PAD + k0 + kq];
                afrag[mt][2] = sAb[i * PAD + k0 + kq + 4];
                afrag[mt][3] = sAb[(i + 8) * PAD + k0 + kq + 4];
            }
            uint32_t bfrag[8][2];
#pragma unroll
            for (int nt = 0; nt < 8; nt++) {
                int n = warp_n * 64 + nt * 8 + gr;
                bfrag[nt][0] = sBb[n * PAD + k0 + kq];
                bfrag[nt][1] = sBb[n * PAD + k0 + kq + 4];
            }
#pragma unroll
            for (int mt = 0; mt < 2; mt++)
#pragma unroll
                for (int nt = 0; nt < 8; nt++)
                    mma_tf32(acc[mt][nt], afrag[mt], bfrag[nt]);
        }
    }

    // ---- denominators ----
#pragma unroll
    for (int ii = 0; ii < 16; ii++) {
        float v = den[ii];
#pragma unroll
        for (int o = 16; o; o >>= 1) v += __shfl_xor_sync(0xffffffffu, v, o);
        if (lane == 0) shDen[wid * 16 + ii] = v;
    }
    __syncthreads();

    // ---- epilogue: normalize, ELU, store ----
#pragma unroll
    for (int mt = 0; mt < 2; mt++) {
        int   rA   = warp_m * 32 + mt * 16 + gr;
        int   rB   = rA + 8;
        float invA = 1.f / shDen[rA];
        float invB = 1.f / shDen[rB];
        float* oA  = out + ((size_t)(b * NN + i0 + rA)) * HH + warp_n * 64;
        float* oB  = out + ((size_t)(b * NN + i0 + rB)) * HH + warp_n * 64;
#pragma unroll
        for (int nt = 0; nt < 8; nt++) {
            float v0 = acc[mt][nt][0] * invA;
            float v1 = acc[mt][nt][1] * invA;
            float v2 = acc[mt][nt][2] * invB;
            float v3 = acc[mt][nt][3] * invB;
            float2 pA, pB;
            pA.x = (v0 > 0.f) ? v0 : expm1f(v0);
            pA.y = (v1 > 0.f) ? v1 : expm1f(v1);
            pB.x = (v2 > 0.f) ? v2 : expm1f(v2);
            pB.y = (v3 > 0.f) ? v3 : expm1f(v3);
            *(float2*)&oA[nt * 8 + kq * 2] = pA;
            *(float2*)&oB[nt * 8 + kq * 2] = pB;
        }
    }
}

// ============================================================================
// Launch
// ============================================================================
extern "C" void kernel_launch(void* const* d_in, const int* in_sizes, int n_in,
                              void* d_out, int out_size) {
    const float* x   = (const float*)d_in[0];  // [8, 2048, 256]
    const float* adj = (const float*)d_in[1];  // [8, 2048, 2048]
    const float* W   = (const float*)d_in[2];  // [128, 256]
    const float* a   = (const float*)d_in[3];  // [256]
    float*       out = (float*)d_out;          // [8, 2048, 128]

    cudaFuncSetAttribute(k3_attn, cudaFuncAttributeMaxDynamicSharedMemorySize,
                         K3_SMEM);

    k1_hgemm<<<dim3(NN / 128, BS), 256>>>(x, W, a);
    k3_attn<<<dim3(NN / 128, BS), 256, K3_SMEM>>>(adj, out);
}

// round 8
// speedup vs baseline: 3.7273x; 1.2469x over previous
#include <cuda_runtime.h>
#include <cstdint>

// Problem constants
#define BS    8
#define NN    2048
#define DIN   256
#define HH    128
#define ALPHA 0.2f

// Scratch (device globals: no allocation allowed)
__device__ float g_ht[BS * HH * NN];   // 8 MB: h^T [b][c][n], tf32-rounded
__device__ float g_ss[BS * NN];        // s_self
__device__ float g_sn[BS * NN];        // s_nb

static __device__ __forceinline__ uint32_t smem_u32(const void* p) {
    uint32_t r;
    asm("{ .reg .u64 t; cvta.to.shared.u64 t, %1; cvt.u32.u64 %0, t; }"
        : "=r"(r) : "l"(p));
    return r;
}

static __device__ __forceinline__ uint32_t tf32rn(float x) {
    uint32_t r;
    asm("cvt.rna.tf32.f32 %0, %1;" : "=r"(r) : "f"(x));
    return r;
}

#define CP_ASYNC16(dst_u32, src_ptr) \
    asm volatile("cp.async.cg.shared.global [%0], [%1], 16;" \
                 :: "r"(dst_u32), "l"(src_ptr) : "memory")
#define CP_COMMIT()  asm volatile("cp.async.commit_group;" ::: "memory")
#define CP_WAIT(n)   asm volatile("cp.async.wait_group %0;" :: "n"(n) : "memory")

#define BAR_SYNC(id, cnt) \
    asm volatile("bar.sync %0, %1;" :: "r"(id), "r"(cnt) : "memory")
#define BAR_ARRIVE(id, cnt) \
    asm volatile("bar.arrive %0, %1;" :: "r"(id), "r"(cnt) : "memory")

// Named barrier ids
#define FULL0 1   // 1,2,3 : stage full  (producers arrive, consumers sync)
#define FREE0 4   // 4,5,6 : stage free  (consumers arrive, producers sync)
#define PBAR  7   // producers-only

// D += A(16x8 row-major) * B(8x8 col-major), tf32 in, fp32 accum
static __device__ __forceinline__ void mma_tf32(float* c, const uint32_t* a,
                                                const uint32_t* b) {
    asm volatile(
        "mma.sync.aligned.m16n8k8.row.col.f32.tf32.tf32.f32 "
        "{%0,%1,%2,%3}, {%4,%5,%6,%7}, {%8,%9}, {%0,%1,%2,%3};"
        : "+f"(c[0]), "+f"(c[1]), "+f"(c[2]), "+f"(c[3])
        : "r"(a[0]), "r"(a[1]), "r"(a[2]), "r"(a[3]), "r"(b[0]), "r"(b[1]));
}

#define PAD 36  // row stride (floats): conflict-free frag LDS + 16B rows

// ============================================================================
// Kernel 1: h = x @ W^T on tf32 mma. CTA: 128 n-rows x 128 c-cols, K=256.
// Epilogue: scatter tf32(h) to g_ht (transposed) + fused ss/sn dots.
// ============================================================================
__global__ __launch_bounds__(256) void k1_hgemm(const float* __restrict__ x,
                                                const float* __restrict__ W,
                                                const float* __restrict__ a) {
    __shared__ uint32_t sA[128][PAD];   // x tile  [n][d]
    __shared__ uint32_t sB[128][PAD];   // W tile  [c][d]
    __shared__ float sh_ps[2][128];
    __shared__ float sh_pn[2][128];

    const int b    = blockIdx.y;
    const int row0 = blockIdx.x * 128;
    const int tid  = threadIdx.x;
    const int lane = tid & 31;
    const int gr   = lane >> 2;
    const int kq   = lane & 3;
    const int warp_m = (tid >> 5) & 3;
    const int warp_n = tid >> 7;

    float acc[2][8][4];
#pragma unroll
    for (int mt = 0; mt < 2; mt++)
#pragma unroll
        for (int nt = 0; nt < 8; nt++)
#pragma unroll
            for (int q = 0; q < 4; q++) acc[mt][nt][q] = 0.f;

    const float* xb = x + ((size_t)b * NN + row0) * DIN;

    for (int d0 = 0; d0 < DIN; d0 += 32) {
        __syncthreads();
#pragma unroll
        for (int p = 0; p < 4; p++) {
            int flat = p * 256 + tid;   // 0..1023
            int row  = flat >> 3;
            int q8   = flat & 7;
            float4 xv = *(const float4*)(xb + (size_t)row * DIN + d0 + q8 * 4);
            uint4 u;
            u.x = tf32rn(xv.x); u.y = tf32rn(xv.y);
            u.z = tf32rn(xv.z); u.w = tf32rn(xv.w);
            *(uint4*)&sA[row][q8 * 4] = u;
            float4 wv = *(const float4*)(W + (size_t)row * DIN + d0 + q8 * 4);
            u.x = tf32rn(wv.x); u.y = tf32rn(wv.y);
            u.z = tf32rn(wv.z); u.w = tf32rn(wv.w);
            *(uint4*)&sB[row][q8 * 4] = u;
        }
        __syncthreads();

#pragma unroll
        for (int k0 = 0; k0 < 32; k0 += 8) {
            uint32_t afrag[2][4];
#pragma unroll
            for (int mt = 0; mt < 2; mt++) {
                int i = warp_m * 32 + mt * 16 + gr;
                afrag[mt][0] = sA[i][k0 + kq];
                afrag[mt][1] = sA[i + 8][k0 + kq];
                afrag[mt][2] = sA[i][k0 + kq + 4];
                afrag[mt][3] = sA[i + 8][k0 + kq + 4];
            }
            uint32_t bfrag[8][2];
#pragma unroll
            for (int nt = 0; nt < 8; nt++) {
                int n = warp_n * 64 + nt * 8 + gr;
                bfrag[nt][0] = sB[n][k0 + kq];
                bfrag[nt][1] = sB[n][k0 + kq + 4];
            }
#pragma unroll
            for (int mt = 0; mt < 2; mt++)
#pragma unroll
                for (int nt = 0; nt < 8; nt++)
                    mma_tf32(acc[mt][nt], afrag[mt], bfrag[nt]);
        }
    }

    // ---- epilogue: scatter h^T (tf32-rounded) + ss/sn partial dots ----
    float* htb = g_ht + (size_t)b * HH * NN;
    float psA[2] = {0.f, 0.f}, pnA[2] = {0.f, 0.f};
    float psB[2] = {0.f, 0.f}, pnB[2] = {0.f, 0.f};
#pragma unroll
    for (int mt = 0; mt < 2; mt++) {
        int nA = row0 + warp_m * 32 + mt * 16 + gr;
        int nB = nA + 8;
#pragma unroll
        for (int nt = 0; nt < 8; nt++) {
            int c0 = warp_n * 64 + nt * 8 + kq * 2;
            float as0 = a[c0], as1 = a[c0 + 1];
            float an0 = a[HH + c0], an1 = a[HH + c0 + 1];
            float v0 = acc[mt][nt][0], v1 = acc[mt][nt][1];
            float v2 = acc[mt][nt][2], v3 = acc[mt][nt][3];
            psA[mt] += v0 * as0 + v1 * as1;
            pnA[mt] += v0 * an0 + v1 * an1;
            psB[mt] += v2 * as0 + v3 * as1;
            pnB[mt] += v2 * an0 + v3 * an1;
            htb[(size_t)c0 * NN + nA]       = __uint_as_float(tf32rn(v0));
            htb[(size_t)(c0 + 1) * NN + nA] = __uint_as_float(tf32rn(v1));
            htb[(size_t)c0 * NN + nB]       = __uint_as_float(tf32rn(v2));
            htb[(size_t)(c0 + 1) * NN + nB] = __uint_as_float(tf32rn(v3));
        }
    }
#pragma unroll
    for (int o = 1; o <= 2; o <<= 1) {
#pragma unroll
        for (int mt = 0; mt < 2; mt++) {
            psA[mt] += __shfl_xor_sync(0xffffffffu, psA[mt], o);
            pnA[mt] += __shfl_xor_sync(0xffffffffu, pnA[mt], o);
            psB[mt] += __shfl_xor_sync(0xffffffffu, psB[mt], o);
            pnB[mt] += __shfl_xor_sync(0xffffffffu, pnB[mt], o);
        }
    }
    if (kq == 0) {
#pragma unroll
        for (int mt = 0; mt < 2; mt++) {
            int rA = warp_m * 32 + mt * 16 + gr;
            sh_ps[warp_n][rA]     = psA[mt];
            sh_pn[warp_n][rA]     = pnA[mt];
            sh_ps[warp_n][rA + 8] = psB[mt];
            sh_pn[warp_n][rA + 8] = pnB[mt];
        }
    }
    __syncthreads();
    if (tid < 128) {
        g_ss[b * NN + row0 + tid] = sh_ps[0][tid] + sh_ps[1][tid];
        g_sn[b * NN + row0 + tid] = sh_pn[0][tid] + sh_pn[1][tid];
    }
}

// ============================================================================
// Kernel 3: warp-specialized masked-softmax aggregation (tf32 mma.sync).
// 512 threads: warps 0-7 consumers (MMA+epilogue), warps 8-15 producers
// (cp.async adj/B, factored-exp w-gen, denominators). Triple-buffered stages.
// ============================================================================
#define K3_CH 64   // chunks of 32 over K=2048
#define ST    3    // stages
#define STA_BYTES (128*PAD*4)    // 18432
#define ADJ_BYTES (128*32*4)     // 16384
// dynamic smem layout (bytes)
#define OFF_SA   0                           // u32[ST][128*PAD]
#define OFF_SB   (OFF_SA + ST*STA_BYTES)
#define OFF_ADJ  (OFF_SB + ST*STA_BYTES)     // f32[ST][128*32]
#define OFF_F    (OFF_ADJ + ST*ADJ_BYTES)    // f32[2048]
#define OFF_H    (OFF_F + 2048*4)            // f32[2048]
#define OFF_EG   (OFF_H + 2048*4)            // float2[128]
#define OFF_DEN  (OFF_EG + 128*8)            // f32[128]
#define K3_SMEM  (OFF_DEN + 128*4)

__global__ __launch_bounds__(512) void k3_attn(const float* __restrict__ adj,
                                               float* __restrict__ out) {
    extern __shared__ char dsm[];
    const uint32_t smb = smem_u32(dsm);

    uint32_t* smA   = (uint32_t*)(dsm + OFF_SA);
    uint32_t* smB   = (uint32_t*)(dsm + OFF_SB);
    float*    smAdj = (float*)(dsm + OFF_ADJ);
    float*    shF   = (float*)(dsm + OFF_F);
    float*    shH   = (float*)(dsm + OFF_H);
    float2*   shEG  = (float2*)(dsm + OFF_EG);
    float*    shDen = (float*)(dsm + OFF_DEN);

    const int b    = blockIdx.y;
    const int i0   = blockIdx.x * 128;
    const int tid  = threadIdx.x;
    const int wid  = tid >> 5;
    const int lane = tid & 31;

    const float* adjb = adj + ((size_t)b * NN + i0) * NN;
    const float* htb  = g_ht + (size_t)b * HH * NN;

    // ---- producer prologue: issue chunks 0,1 (before tables, hide DRAM) ----
    const int ptid = tid & 255;          // producer-local id (only used wid>=8)
    const int cq   = ptid & 7;
    int crow[4];
#pragma unroll
    for (int p = 0; p < 4; p++) crow[p] = (p * 256 + ptid) >> 3;

    if (wid >= 8) {
#pragma unroll
        for (int c0 = 0; c0 < 2; c0++) {
#pragma unroll
            for (int p = 0; p < 4; p++) {
                int r = crow[p];
                CP_ASYNC16(smb + OFF_ADJ + c0 * ADJ_BYTES + (r * 32 + cq * 4) * 4,
                           adjb + (size_t)r * NN + c0 * 32 + cq * 4);
                CP_ASYNC16(smb + OFF_SB + c0 * STA_BYTES + (r * PAD + cq * 4) * 4,
                           htb + (size_t)r * NN + c0 * 32 + cq * 4);
            }
            CP_COMMIT();
        }
    }

    // ---- tables (all 512 threads) ----
#pragma unroll
    for (int p = 0; p < 4; p++) {
        int j = p * 512 + tid;
        float sn = g_sn[b * NN + j];
        shF[j] = expf(sn);
        shH[j] = expf(0.2f * sn);
    }
    if (tid < 128) {
        float ss = g_ss[b * NN + i0 + tid];
        shEG[tid] = make_float2(expf(ss), expf(0.2f * ss));
    }
    __syncthreads();

    if (wid >= 8) {
        // ================= PRODUCER =================
        const int pw = wid - 8;          // 0..7, rows pw*16..+15
        float den[16];
#pragma unroll
        for (int q = 0; q < 16; q++) den[q] = 0.f;

        for (int g = 0; g < K3_CH; g++) {
            const int s = g % ST;
            if (g < K3_CH - 1) CP_WAIT(1); else CP_WAIT(0);
            BAR_SYNC(PBAR, 256);        // chunk g adj+B visible to all producers

            // gen w tile into sA[s]
            {
                float F = shF[g * 32 + lane];
                float H = shH[g * 32 + lane];
                float*    adjS = smAdj + s * (128 * 32);
                uint32_t* aS   = smA + s * (128 * PAD);
#pragma unroll
                for (int ii = 0; ii < 16; ii++) {
                    int    r  = pw * 16 + ii;
                    float  av = adjS[r * 32 + lane];
                    float2 eg = shEG[r];
                    float  pp = eg.x * F;
                    float  w  = av * ((pp >= 1.f) ? pp : eg.y * H);
                    uint32_t wr = tf32rn(w);
                    den[ii] += __uint_as_float(wr);
                    aS[r * PAD + lane] = wr;
                }
            }
            BAR_ARRIVE(FULL0 + s, 512);

            // prefetch chunk g+2 into stage (g+2)%ST
            if (g + 2 < K3_CH) {
                const int s2 = (g + 2) % ST;
                if (g >= 1) BAR_SYNC(FREE0 + s2, 512);  // consumer g-1 done
                const int j2 = (g + 2) * 32;
#pragma unroll
                for (int p = 0; p < 4; p++) {
                    int r = crow[p];
                    CP_ASYNC16(smb + OFF_ADJ + s2 * ADJ_BYTES + (r * 32 + cq * 4) * 4,
                               adjb + (size_t)r * NN + j2 + cq * 4);
                    CP_ASYNC16(smb + OFF_SB + s2 * STA_BYTES + (r * PAD + cq * 4) * 4,
                               htb + (size_t)r * NN + j2 + cq * 4);
                }
                CP_COMMIT();
            }
        }

        // denominators -> shDen
#pragma unroll
        for (int ii = 0; ii < 16; ii++) {
            float v = den[ii];
#pragma unroll
            for (int o = 16; o; o >>= 1) v += __shfl_xor_sync(0xffffffffu, v, o);
            if (lane == 0) shDen[pw * 16 + ii] = v;
        }
        __syncthreads();
        // producers done
    } else {
        // ================= CONSUMER =================
        const int gr     = lane >> 2;
        const int kq     = lane & 3;
        const int warp_m = wid & 3;
        const int warp_n = wid >> 2;

        float acc[2][8][4];
#pragma unroll
        for (int mt = 0; mt < 2; mt++)
#pragma unroll
            for (int nt = 0; nt < 8; nt++)
#pragma unroll
                for (int q = 0; q < 4; q++) acc[mt][nt][q] = 0.f;

        for (int t = 0; t < K3_CH; t++) {
            const int s = t % ST;
            BAR_SYNC(FULL0 + s, 512);
            uint32_t* sAb = smA + s * (128 * PAD);
            uint32_t* sBb = smB + s * (128 * PAD);
#pragma unroll
            for (int k0 = 0; k0 < 32; k0 += 8) {
                uint32_t afrag[2][4];
#pragma unroll
                for (int mt = 0; mt < 2; mt++) {
                    int i = warp_m * 32 + mt * 16 + gr;
                    afrag[mt][0] = sAb[i * PAD + k0 + kq];
                    afrag[mt][1] = sAb[(i + 8) * PAD + k0 + kq];
                    afrag[mt][2] = sAb[i * PAD + k0 + kq + 4];
                    afrag[mt][3] = sAb[(i + 8) * PAD + k0 + kq + 4];
                }
                uint32_t bfrag[8][2];
#pragma unroll
                for (int nt = 0; nt < 8; nt++) {
                    int n = warp_n * 64 + nt * 8 + gr;
                    bfrag[nt][0] = sBb[n * PAD + k0 + kq];
                    bfrag[nt][1] = sBb[n * PAD + k0 + kq + 4];
                }
#pragma unroll
                for (int mt = 0; mt < 2; mt++)
#pragma unroll
                    for (int nt = 0; nt < 8; nt++)
                        mma_tf32(acc[mt][nt], afrag[mt], bfrag[nt]);
            }
            if (t < K3_CH - ST) BAR_ARRIVE(FREE0 + s, 512);
        }
        __syncthreads();  // shDen ready (producers wrote it)

        // ---- epilogue: normalize, ELU, store ----
#pragma unroll
        for (int mt = 0; mt < 2; mt++) {
            int   rA   = warp_m * 32 + mt * 16 + gr;
            int   rB   = rA + 8;
            float invA = 1.f / shDen[rA];
            float invB = 1.f / shDen[rB];
            float* oA  = out + ((size_t)(b * NN + i0 + rA)) * HH + warp_n * 64;
            float* oB  = out + ((size_t)(b * NN + i0 + rB)) * HH + warp_n * 64;
#pragma unroll
            for (int nt = 0; nt < 8; nt++) {
                float v0 = acc[mt][nt][0] * invA;
                float v1 = acc[mt][nt][1] * invA;
                float v2 = acc[mt][nt][2] * invB;
                float v3 = acc[mt][nt][3] * invB;
                float2 pA, pB;
                pA.x = (v0 > 0.f) ? v0 : expm1f(v0);
                pA.y = (v1 > 0.f) ? v1 : expm1f(v1);
                pB.x = (v2 > 0.f) ? v2 : expm1f(v2);
                pB.y = (v3 > 0.f) ? v3 : expm1f(v3);
                *(float2*)&oA[nt * 8 + kq * 2] = pA;
                *(float2*)&oB[nt * 8 + kq * 2] = pB;
            }
        }
    }
}

// ============================================================================
// Launch
// ============================================================================
extern "C" void kernel_launch(void* const* d_in, const int* in_sizes, int n_in,
                              void* d_out, int out_size) {
    const float* x   = (const float*)d_in[0];  // [8, 2048, 256]
    const float* adj = (const float*)d_in[1];  // [8, 2048, 2048]
    const float* W   = (const float*)d_in[2];  // [128, 256]
    const float* a   = (const float*)d_in[3];  // [256]
    float*       out = (float*)d_out;          // [8, 2048, 128]

    cudaFuncSetAttribute(k3_attn, cudaFuncAttributeMaxDynamicSharedMemorySize,
                         K3_SMEM);

    k1_hgemm<<<dim3(NN / 128, BS), 256>>>(x, W, a);
    k3_attn<<<dim3(NN / 128, BS), 512, K3_SMEM>>>(adj, out);
}